// round 2
// baseline (speedup 1.0000x reference)
#include <cuda_runtime.h>

#define N_T   4096
#define N_D   256
#define N_B   16
#define NCOL  (N_B * N_D)   // 4096 columns (b,d)
#define TOPK  7
#define TWO_PI 6.28318530717958647692f

// Per-column selected-frequency parameters (scratch; device globals per rules)
__device__ float g_Ac[NCOL * TOPK];
__device__ float g_As[NCOL * TOPK];
__device__ int   g_idx[NCOL * TOPK];

// ---------------------------------------------------------------------------
// Kernel A: per-column 4096-pt FFT (radix-2 DIF, bit-reversed output) + top-7
// ---------------------------------------------------------------------------
__global__ __launch_bounds__(256) void fft_topk_kernel(const float* __restrict__ x) {
    __shared__ float s_re[N_T];
    __shared__ float s_im[N_T];
    __shared__ float s_tab[2049];   // cos(2*pi*m/4096), m=0..2048; reused as mag[2048]
    __shared__ float s_redv[8];
    __shared__ int   s_redi[8];

    const int tid = threadIdx.x;
    const int col = blockIdx.x;
    const int b = col >> 8;
    const int d = col & 255;
    const float* xp = x + ((size_t)b * N_T) * N_D + d;

    // quarter-wave-capable cos table (sin(2*pi*j/4096) = tab[|j-1024|] for j<=2048)
    for (int m = tid; m <= 2048; m += 256)
        s_tab[m] = __cosf((float)m * (TWO_PI / (float)N_T));

    // load column (strided in gmem; neighboring CTAs share lines -> L2 reuse)
    for (int t = tid; t < N_T; t += 256) {
        s_re[t] = xp[(size_t)t * N_D];
        s_im[t] = 0.0f;
    }
    __syncthreads();

    // 12-stage radix-2 DIF FFT, in place, natural input -> bit-reversed output
    #pragma unroll 1
    for (int stage = 0; stage < 12; stage++) {
        const int half = 2048 >> stage;
        #pragma unroll 1
        for (int k = tid; k < 2048; k += 256) {
            const int j  = k & (half - 1);
            const int i0 = (k << 1) - j;
            const int i1 = i0 + half;
            const int tj = j << stage;          // twiddle index into 4096-cycle
            float ar = s_re[i0], ai = s_im[i0];
            float br = s_re[i1], bi = s_im[i1];
            float dr = ar - br,  di = ai - bi;
            s_re[i0] = ar + br;
            s_im[i0] = ai + bi;
            float wr =  s_tab[tj];              // cos(theta)
            float wi = -s_tab[abs(tj - 1024)];  // -sin(theta)
            s_re[i1] = dr * wr - di * wi;
            s_im[i1] = dr * wi + di * wr;
        }
        __syncthreads();
    }

    // magnitudes^2 of bins f=1..2047 (bin f lives at bit-reversed position)
    for (int f = tid; f < 2048; f += 256) {
        float m2 = -1.0f;
        if (f != 0) {
            const int p = __brev((unsigned)f) >> 20;   // 12-bit bit reversal
            const float re = s_re[p], im = s_im[p];
            m2 = re * re + im * im;
        }
        s_tab[f] = m2;   // cos table dead after FFT; reuse as mag[]
    }
    __syncthreads();

    // 7 rounds of block argmax (ties -> lowest index, matching lax.top_k)
    float* mag = s_tab;
    for (int sel = 0; sel < TOPK; sel++) {
        float bv = -1e30f; int bi = 0;
        for (int f = tid; f < 2048; f += 256) {
            const float v = mag[f];
            if (v > bv) { bv = v; bi = f; }    // ascending scan -> keeps lowest idx
        }
        #pragma unroll
        for (int off = 16; off > 0; off >>= 1) {
            const float ov = __shfl_down_sync(0xffffffffu, bv, off);
            const int   oi = __shfl_down_sync(0xffffffffu, bi, off);
            if (ov > bv || (ov == bv && oi < bi)) { bv = ov; bi = oi; }
        }
        if ((tid & 31) == 0) { s_redv[tid >> 5] = bv; s_redi[tid >> 5] = bi; }
        __syncthreads();
        if (tid == 0) {
            for (int w = 1; w < 8; w++) {
                const float ov = s_redv[w]; const int oi = s_redi[w];
                if (ov > bv || (ov == bv && oi < bi)) { bv = ov; bi = oi; }
            }
            const int p = __brev((unsigned)bi) >> 20;
            const float sc = 4.0f / (float)N_T;   // 2/T from amp, 2x from conj pair
            g_Ac[col * TOPK + sel]  = sc * s_re[p];   // A*cos(phi) = (4/T)*Re
            g_As[col * TOPK + sel]  = sc * s_im[p];   // A*sin(phi) = (4/T)*Im
            g_idx[col * TOPK + sel] = bi;
            mag[bi] = -1e30f;
        }
        __syncthreads();
    }
}

// ---------------------------------------------------------------------------
// Kernel B: reconstruction. out[b,t,d] = sum_k Ac*cos(a) - As*sin(a),
//   a = 2*pi*((idx_k * t) mod 4096)/4096. Integer phase accumulator + SMEM LUT.
// Grid: (128 t-tiles of 32, 16 b). threadIdx.x = d (coalesced stores).
// ---------------------------------------------------------------------------
__global__ __launch_bounds__(256) void recon_kernel(float* __restrict__ out) {
    __shared__ float2 tab[N_T];   // {cos, sin}(2*pi*m/4096)

    const int tid = threadIdx.x;
    for (int m = tid; m < N_T; m += 256) {
        float s, c;
        __sincosf((float)m * (TWO_PI / (float)N_T), &s, &c);
        tab[m] = make_float2(c, s);
    }
    __syncthreads();

    const int b  = blockIdx.y;
    const int t0 = blockIdx.x * 32;
    const int d  = tid;
    const int col = b * N_D + d;

    float Ac[TOPK], Asn[TOPK];
    int   idx[TOPK], m[TOPK];
    #pragma unroll
    for (int k = 0; k < TOPK; k++) {
        Ac[k]  =  g_Ac[col * TOPK + k];
        Asn[k] = -g_As[col * TOPK + k];
        idx[k] =  g_idx[col * TOPK + k];
        m[k]   = (idx[k] * t0) & (N_T - 1);
    }

    float* outp = out + ((size_t)b * N_T + t0) * N_D + d;
    #pragma unroll 4
    for (int tt = 0; tt < 32; tt++) {
        float acc = 0.0f;
        #pragma unroll
        for (int k = 0; k < TOPK; k++) {
            const float2 cs = tab[m[k]];
            acc = fmaf(Ac[k],  cs.x, acc);
            acc = fmaf(Asn[k], cs.y, acc);
            m[k] = (m[k] + idx[k]) & (N_T - 1);
        }
        outp[(size_t)tt * N_D] = acc;
    }
}

// ---------------------------------------------------------------------------
extern "C" void kernel_launch(void* const* d_in, const int* in_sizes, int n_in,
                              void* d_out, int out_size) {
    const float* x = (const float*)d_in[0];
    float* out = (float*)d_out;

    fft_topk_kernel<<<NCOL, 256>>>(x);
    recon_kernel<<<dim3(N_T / 32, N_B), 256>>>(out);
}

// round 4
// speedup vs baseline: 1.1936x; 1.1936x over previous
#include <cuda_runtime.h>

#define N_T   4096
#define N_D   256
#define N_B   16
#define NCOL  (N_B * N_D)   // 4096 columns (b,d)
#define TOPK  7
#define TWO_PI 6.28318530717958647692f

// Per-column selected-frequency parameters (scratch; device globals per rules)
__device__ float g_Ac[NCOL * TOPK];
__device__ float g_As[NCOL * TOPK];
__device__ int   g_idx[NCOL * TOPK];

// Precomputed trig tables (built once per launch by init_tables):
//  g_tw : per-stage DIF twiddles, stage s at offset 4096-(4096>>s), entry j =
//         { cos(2*pi*(j<<s)/4096), -sin(2*pi*(j<<s)/4096) }  (consecutive in j!)
//  g_cs : master table { cos(2*pi*m/4096), sin(2*pi*m/4096) } for reconstruction
__device__ float2 g_tw[4096];
__device__ float2 g_cs[N_T];

// ---------------------------------------------------------------------------
// Kernel 0: build trig tables once (16 CTAs x 256 thr = 4096 threads, ~2us)
// ---------------------------------------------------------------------------
__global__ __launch_bounds__(256) void init_tables() {
    const int gtid = blockIdx.x * 256 + threadIdx.x;   // 0..4095
    float s, c;
    sincosf((float)gtid * (TWO_PI / (float)N_T), &s, &c);
    g_cs[gtid] = make_float2(c, s);

    #pragma unroll 1
    for (int st = 0; st < 12; st++) {
        const int half = 2048 >> st;
        if (gtid < half) {
            const int toff = 4096 - (4096 >> st);
            float ss, cc;
            sincosf((float)(gtid << st) * (TWO_PI / (float)N_T), &ss, &cc);
            g_tw[toff + gtid] = make_float2(cc, -ss);
        }
    }
}

// ---------------------------------------------------------------------------
// Kernel A: per-column 4096-pt FFT (radix-2 DIF, bit-reversed output) + top-7
// Twiddles come from gmem (L1-resident, coalesced in j) -> no bank conflicts.
// ---------------------------------------------------------------------------
__global__ __launch_bounds__(256) void fft_topk_kernel(const float* __restrict__ x) {
    __shared__ float s_re[N_T];
    __shared__ float s_im[N_T];
    __shared__ float s_mag[2048];
    __shared__ float s_redv[8];
    __shared__ int   s_redi[8];

    const int tid = threadIdx.x;
    const int col = blockIdx.x;
    const int b = col >> 8;
    const int d = col & 255;
    const float* xp = x + ((size_t)b * N_T) * N_D + d;

    // load column (strided in gmem; neighboring CTAs share lines -> L2 reuse)
    for (int t = tid; t < N_T; t += 256) {
        s_re[t] = __ldg(xp + (size_t)t * N_D);
        s_im[t] = 0.0f;
    }
    __syncthreads();

    // 12-stage radix-2 DIF FFT, in place, natural input -> bit-reversed output
    #pragma unroll 1
    for (int stage = 0; stage < 12; stage++) {
        const int half = 2048 >> stage;
        const int toff = 4096 - (4096 >> stage);
        #pragma unroll 1
        for (int k = tid; k < 2048; k += 256) {
            const int j  = k & (half - 1);
            const int i0 = (k << 1) - j;
            const int i1 = i0 + half;
            float ar = s_re[i0], ai = s_im[i0];
            float br = s_re[i1], bi = s_im[i1];
            float dr = ar - br,  di = ai - bi;
            s_re[i0] = ar + br;
            s_im[i0] = ai + bi;
            const float2 w = __ldg(&g_tw[toff + j]);   // (cos, -sin), coalesced
            s_re[i1] = dr * w.x - di * w.y;
            s_im[i1] = dr * w.y + di * w.x;
        }
        __syncthreads();
    }

    // magnitudes^2 of bins f=1..2047 (bin f lives at bit-reversed position)
    for (int f = tid; f < 2048; f += 256) {
        float m2 = -1.0f;
        if (f != 0) {
            const int p = __brev((unsigned)f) >> 20;   // 12-bit bit reversal
            const float re = s_re[p], im = s_im[p];
            m2 = re * re + im * im;
        }
        s_mag[f] = m2;
    }
    __syncthreads();

    // 7 rounds of block argmax (ties -> lowest index, matching lax.top_k)
    for (int sel = 0; sel < TOPK; sel++) {
        float bv = -1e30f; int bi = 0;
        for (int f = tid; f < 2048; f += 256) {
            const float v = s_mag[f];
            if (v > bv) { bv = v; bi = f; }    // ascending scan -> keeps lowest idx
        }
        #pragma unroll
        for (int off = 16; off > 0; off >>= 1) {
            const float ov = __shfl_down_sync(0xffffffffu, bv, off);
            const int   oi = __shfl_down_sync(0xffffffffu, bi, off);
            if (ov > bv || (ov == bv && oi < bi)) { bv = ov; bi = oi; }
        }
        if ((tid & 31) == 0) { s_redv[tid >> 5] = bv; s_redi[tid >> 5] = bi; }
        __syncthreads();
        if (tid == 0) {
            for (int w = 1; w < 8; w++) {
                const float ov = s_redv[w]; const int oi = s_redi[w];
                if (ov > bv || (ov == bv && oi < bi)) { bv = ov; bi = oi; }
            }
            const int p = __brev((unsigned)bi) >> 20;
            const float sc = 4.0f / (float)N_T;   // 2/T from amp, 2x from conj pair
            g_Ac[col * TOPK + sel]  = sc * s_re[p];   // A*cos(phi) = (4/T)*Re
            g_As[col * TOPK + sel]  = sc * s_im[p];   // A*sin(phi) = (4/T)*Im
            g_idx[col * TOPK + sel] = bi;
            s_mag[bi] = -1e30f;
        }
        __syncthreads();
    }
}

// ---------------------------------------------------------------------------
// Kernel B: reconstruction. out[b,t,d] = sum_k Ac*cos(a) - As*sin(a),
//   a = 2*pi*((idx_k * t) mod 4096)/4096. Integer phase accumulator + SMEM LUT
//   copied from the precomputed gmem table (no per-CTA sincosf!).
// Grid: (128 t-tiles of 32, 16 b). threadIdx.x = d (coalesced stores).
// ---------------------------------------------------------------------------
__global__ __launch_bounds__(256) void recon_kernel(float* __restrict__ out) {
    __shared__ float2 tab[N_T];   // {cos, sin}(2*pi*m/4096)

    const int tid = threadIdx.x;
    for (int m = tid; m < N_T; m += 256)
        tab[m] = __ldg(&g_cs[m]);
    __syncthreads();

    const int b  = blockIdx.y;
    const int t0 = blockIdx.x * 32;
    const int d  = tid;
    const int col = b * N_D + d;

    float Ac[TOPK], Asn[TOPK];
    int   idx[TOPK], m[TOPK];
    #pragma unroll
    for (int k = 0; k < TOPK; k++) {
        Ac[k]  =  g_Ac[col * TOPK + k];
        Asn[k] = -g_As[col * TOPK + k];
        idx[k] =  g_idx[col * TOPK + k];
        m[k]   = (idx[k] * t0) & (N_T - 1);
    }

    float* outp = out + ((size_t)b * N_T + t0) * N_D + d;
    #pragma unroll 4
    for (int tt = 0; tt < 32; tt++) {
        float acc = 0.0f;
        #pragma unroll
        for (int k = 0; k < TOPK; k++) {
            const float2 cs = tab[m[k]];
            acc = fmaf(Ac[k],  cs.x, acc);
            acc = fmaf(Asn[k], cs.y, acc);
            m[k] = (m[k] + idx[k]) & (N_T - 1);
        }
        outp[(size_t)tt * N_D] = acc;
    }
}

// ---------------------------------------------------------------------------
extern "C" void kernel_launch(void* const* d_in, const int* in_sizes, int n_in,
                              void* d_out, int out_size) {
    const float* x = (const float*)d_in[0];
    float* out = (float*)d_out;

    init_tables<<<16, 256>>>();
    fft_topk_kernel<<<NCOL, 256>>>(x);
    recon_kernel<<<dim3(N_T / 32, N_B), 256>>>(out);
}

// round 5
// speedup vs baseline: 2.4389x; 2.0433x over previous
#include <cuda_runtime.h>

#define N_T   4096
#define N_D   256
#define N_B   16
#define NCOL  (N_B * N_D)   // 4096 columns (b,d)
#define TOPK  7
#define TWO_PI 6.28318530717958647692f

// Per-column selected-frequency parameters (scratch; device globals per rules)
__device__ float g_Ac[NCOL * TOPK];
__device__ float g_As[NCOL * TOPK];
__device__ int   g_idx[NCOL * TOPK];

// cos/sin master table for reconstruction
__device__ float2 g_cs[N_T];

// 64 MB transposed input: g_xT[col][t], col = b*256 + d
__device__ float g_xT[(size_t)NCOL * N_T];

// padded smem index: injective, kills stride-16 conflicts in passes 1/2
#define PAD(n) ((n) + ((n) >> 4))

__device__ __forceinline__ float2 cmul(float2 a, float2 b) {
    return make_float2(fmaf(a.x, b.x, -(a.y * b.y)),
                       fmaf(a.x, b.y,   a.y * b.x));
}
__device__ __forceinline__ float2 cadd(float2 a, float2 b) { return make_float2(a.x + b.x, a.y + b.y); }
__device__ __forceinline__ float2 csub(float2 a, float2 b) { return make_float2(a.x - b.x, a.y - b.y); }

// 16-pt DIF FFT in registers; X[k] ends up in a[bitrev4(k)].
__device__ __forceinline__ void fft16(float2 a[16]) {
    const float c1 = 0.9238795325112867f;   // cos(pi/8)
    const float s1 = 0.3826834323650898f;   // sin(pi/8)
    const float r2 = 0.7071067811865476f;
    const float2 W[8] = { { 1.f, 0.f}, { c1, -s1}, { r2, -r2}, { s1, -c1},
                          { 0.f,-1.f}, {-s1, -c1}, {-r2, -r2}, {-c1, -s1} };
    #pragma unroll
    for (int j = 0; j < 8; j++) {
        float2 u = a[j], v = a[j + 8];
        a[j]     = cadd(u, v);
        a[j + 8] = cmul(csub(u, v), W[j]);
    }
    #pragma unroll
    for (int b = 0; b < 16; b += 8)
        #pragma unroll
        for (int j = 0; j < 4; j++) {
            float2 u = a[b + j], v = a[b + j + 4];
            a[b + j]     = cadd(u, v);
            a[b + j + 4] = cmul(csub(u, v), W[2 * j]);
        }
    #pragma unroll
    for (int b = 0; b < 16; b += 4)
        #pragma unroll
        for (int j = 0; j < 2; j++) {
            float2 u = a[b + j], v = a[b + j + 2];
            float2 t = csub(u, v);
            a[b + j]     = cadd(u, v);
            a[b + j + 2] = (j == 0) ? t : make_float2(t.y, -t.x);   // * (0,-1)
        }
    #pragma unroll
    for (int b = 0; b < 16; b += 2) {
        float2 u = a[b], v = a[b + 1];
        a[b]     = cadd(u, v);
        a[b + 1] = csub(u, v);
    }
}

// ---------------------------------------------------------------------------
// Kernel 0: build cos/sin table for reconstruction (~2us)
// ---------------------------------------------------------------------------
__global__ __launch_bounds__(256) void init_tables() {
    const int gtid = blockIdx.x * 256 + threadIdx.x;   // 0..4095
    float s, c;
    sincosf((float)gtid * (TWO_PI / (float)N_T), &s, &c);
    g_cs[gtid] = make_float2(c, s);
}

// ---------------------------------------------------------------------------
// Kernel T: x[b,t,d] -> g_xT[b*256+d][t] via 32x33 smem tiles (coalesced both ways)
// ---------------------------------------------------------------------------
__global__ __launch_bounds__(256) void transpose_kernel(const float* __restrict__ x) {
    __shared__ float tile[32][33];
    const int b  = blockIdx.z;
    const int tt = blockIdx.x;   // t tile
    const int dd = blockIdx.y;   // d tile
    const int tx = threadIdx.x & 31;
    const int ty = threadIdx.x >> 5;   // 0..7

    const float* xp = x + ((size_t)b * N_T + (size_t)tt * 32) * N_D + (size_t)dd * 32;
    #pragma unroll
    for (int r = 0; r < 32; r += 8)
        tile[ty + r][tx] = xp[(size_t)(ty + r) * N_D + tx];
    __syncthreads();

    float* op = g_xT + ((size_t)(b * N_D + dd * 32)) * N_T + (size_t)tt * 32;
    #pragma unroll
    for (int r = 0; r < 32; r += 8)
        op[(size_t)(ty + r) * N_T + tx] = tile[tx][ty + r];
}

// ---------------------------------------------------------------------------
// Kernel A: per-column 4096-pt FFT (3 radix-16 passes, registers) + top-7
// ---------------------------------------------------------------------------
__global__ __launch_bounds__(256, 4) void fft_topk_kernel() {
    __shared__ float2 s_buf[PAD(4095) + 1];   // 4351 float2 = 34.8 KB
    __shared__ float  s_mag[2048];
    __shared__ float  s_redv[8];
    __shared__ int    s_redi[8];

    const int tid = threadIdx.x;
    const int col = blockIdx.x;
    const float* xp = g_xT + (size_t)col * N_T;

    const int BR[16] = {0,8,4,12,2,10,6,14,1,9,5,13,3,11,7,15};
    float2 a[16];

    // ---- pass 0: DFT over n1 (stride 256), post-twiddle W4096^{tid*k0} ----
    #pragma unroll
    for (int n1 = 0; n1 < 16; n1++)
        a[n1] = make_float2(__ldg(xp + 256 * n1 + tid), 0.0f);   // coalesced
    fft16(a);
    {
        float sn, cn;
        sincosf(-(TWO_PI / 4096.0f) * (float)tid, &sn, &cn);
        const float2 w = make_float2(cn, sn);                    // e^{-2pi i tid/4096}
        float2 tw = make_float2(1.0f, 0.0f);
        #pragma unroll
        for (int r = 0; r < 16; r++) {
            s_buf[PAD(256 * r + tid)] = cmul(a[BR[r]], tw);
            tw = cmul(tw, w);
        }
    }
    __syncthreads();

    // ---- pass 1: DFT over m1 (stride 16), post-twiddle W256^{m0*k1} ----
    const int k0 = tid >> 4, m0 = tid & 15;
    #pragma unroll
    for (int m1 = 0; m1 < 16; m1++)
        a[m1] = s_buf[PAD(256 * k0 + 16 * m1 + m0)];
    fft16(a);
    {
        float sn, cn;
        sincosf(-(TWO_PI / 256.0f) * (float)m0, &sn, &cn);
        const float2 w = make_float2(cn, sn);                    // e^{-2pi i m0/256}
        float2 tw = make_float2(1.0f, 0.0f);
        #pragma unroll
        for (int r = 0; r < 16; r++) {
            s_buf[PAD(256 * k0 + 16 * r + m0)] = cmul(a[BR[r]], tw);   // own slots only
            tw = cmul(tw, w);
        }
    }
    __syncthreads();

    // ---- pass 2: DFT over m0 (stride 1); bin f = k0 + 16*k1 + 256*k2 ----
    const int kk1 = tid & 15;   // k0 is tid>>4 (same var)
    #pragma unroll
    for (int m = 0; m < 16; m++)
        a[m] = s_buf[PAD(256 * k0 + 16 * kk1 + m)];
    fft16(a);
    __syncthreads();   // everyone done reading s_buf before we repurpose it

    // spectrum (f < 2048) back into the dead pass buffer + magnitudes
    const int fbase = k0 + 16 * kk1;
    #pragma unroll
    for (int r = 0; r < 8; r++) {
        const float2 X = a[BR[r]];
        const int f = fbase + 256 * r;
        s_buf[PAD(f)] = X;
        s_mag[f] = (f == 0) ? -1e30f : fmaf(X.x, X.x, X.y * X.y);
    }
    __syncthreads();

    // ---- 7 rounds of block argmax (ties -> lowest index, matching lax.top_k) ----
    for (int sel = 0; sel < TOPK; sel++) {
        float bv = -1e30f; int bi = 0;
        for (int f = tid; f < 2048; f += 256) {
            const float v = s_mag[f];
            if (v > bv) { bv = v; bi = f; }   // ascending scan keeps lowest idx
        }
        #pragma unroll
        for (int off = 16; off > 0; off >>= 1) {
            const float ov = __shfl_down_sync(0xffffffffu, bv, off);
            const int   oi = __shfl_down_sync(0xffffffffu, bi, off);
            if (ov > bv || (ov == bv && oi < bi)) { bv = ov; bi = oi; }
        }
        if ((tid & 31) == 0) { s_redv[tid >> 5] = bv; s_redi[tid >> 5] = bi; }
        __syncthreads();
        if (tid == 0) {
            for (int w = 1; w < 8; w++) {
                const float ov = s_redv[w]; const int oi = s_redi[w];
                if (ov > bv || (ov == bv && oi < bi)) { bv = ov; bi = oi; }
            }
            const float2 X = s_buf[PAD(bi)];
            const float sc = 4.0f / (float)N_T;       // 2/T amp * 2 conj pair
            g_Ac[col * TOPK + sel]  = sc * X.x;       // A*cos(phi) = (4/T)*Re
            g_As[col * TOPK + sel]  = sc * X.y;       // A*sin(phi) = (4/T)*Im
            g_idx[col * TOPK + sel] = bi;
            s_mag[bi] = -1e30f;
        }
        __syncthreads();
    }
}

// ---------------------------------------------------------------------------
// Kernel B: reconstruction. out[b,t,d] = sum_k Ac*cos(a) - As*sin(a),
//   a = 2*pi*((idx_k*t) mod 4096)/4096. Integer phase accumulator + smem LUT
//   copied from the precomputed gmem table.
// ---------------------------------------------------------------------------
__global__ __launch_bounds__(256) void recon_kernel(float* __restrict__ out) {
    __shared__ float2 tab[N_T];

    const int tid = threadIdx.x;
    for (int m = tid; m < N_T; m += 256)
        tab[m] = __ldg(&g_cs[m]);
    __syncthreads();

    const int b  = blockIdx.y;
    const int t0 = blockIdx.x * 32;
    const int d  = tid;
    const int col = b * N_D + d;

    float Ac[TOPK], Asn[TOPK];
    int   idx[TOPK], m[TOPK];
    #pragma unroll
    for (int k = 0; k < TOPK; k++) {
        Ac[k]  =  g_Ac[col * TOPK + k];
        Asn[k] = -g_As[col * TOPK + k];
        idx[k] =  g_idx[col * TOPK + k];
        m[k]   = (idx[k] * t0) & (N_T - 1);
    }

    float* outp = out + ((size_t)b * N_T + t0) * N_D + d;
    #pragma unroll 4
    for (int tt = 0; tt < 32; tt++) {
        float acc = 0.0f;
        #pragma unroll
        for (int k = 0; k < TOPK; k++) {
            const float2 cs = tab[m[k]];
            acc = fmaf(Ac[k],  cs.x, acc);
            acc = fmaf(Asn[k], cs.y, acc);
            m[k] = (m[k] + idx[k]) & (N_T - 1);
        }
        outp[(size_t)tt * N_D] = acc;
    }
}

// ---------------------------------------------------------------------------
extern "C" void kernel_launch(void* const* d_in, const int* in_sizes, int n_in,
                              void* d_out, int out_size) {
    const float* x = (const float*)d_in[0];
    float* out = (float*)d_out;

    init_tables<<<16, 256>>>();
    transpose_kernel<<<dim3(N_T / 32, N_D / 32, N_B), 256>>>(x);
    fft_topk_kernel<<<NCOL, 256>>>();
    recon_kernel<<<dim3(N_T / 32, N_B), 256>>>(out);
}

// round 6
// speedup vs baseline: 4.0897x; 1.6769x over previous
#include <cuda_runtime.h>

#define N_T   4096
#define N_D   256
#define N_B   16
#define NCOL  (N_B * N_D)   // 4096 columns (b,d)
#define TOPK  7
#define TWO_PI 6.28318530717958647692f

// Per-column selected-frequency parameters (scratch; device globals per rules)
__device__ float g_Ac[NCOL * TOPK];
__device__ float g_As[NCOL * TOPK];
__device__ int   g_idx[NCOL * TOPK];

// cos/sin master table for reconstruction
__device__ float2 g_cs[N_T];

// 64 MB transposed input: g_xT[col][t], col = b*256 + d
__device__ float g_xT[(size_t)NCOL * N_T];

// padded smem index: injective, kills stride-16 conflicts in passes 1/2
#define PAD(n) ((n) + ((n) >> 4))

__device__ __forceinline__ float2 cmul(float2 a, float2 b) {
    return make_float2(fmaf(a.x, b.x, -(a.y * b.y)),
                       fmaf(a.x, b.y,   a.y * b.x));
}
__device__ __forceinline__ float2 cadd(float2 a, float2 b) { return make_float2(a.x + b.x, a.y + b.y); }
__device__ __forceinline__ float2 csub(float2 a, float2 b) { return make_float2(a.x - b.x, a.y - b.y); }

// 16-pt DIF FFT in registers; X[k] ends up in a[bitrev4(k)].
__device__ __forceinline__ void fft16(float2 a[16]) {
    const float c1 = 0.9238795325112867f;   // cos(pi/8)
    const float s1 = 0.3826834323650898f;   // sin(pi/8)
    const float r2 = 0.7071067811865476f;
    const float2 W[8] = { { 1.f, 0.f}, { c1, -s1}, { r2, -r2}, { s1, -c1},
                          { 0.f,-1.f}, {-s1, -c1}, {-r2, -r2}, {-c1, -s1} };
    #pragma unroll
    for (int j = 0; j < 8; j++) {
        float2 u = a[j], v = a[j + 8];
        a[j]     = cadd(u, v);
        a[j + 8] = cmul(csub(u, v), W[j]);
    }
    #pragma unroll
    for (int b = 0; b < 16; b += 8)
        #pragma unroll
        for (int j = 0; j < 4; j++) {
            float2 u = a[b + j], v = a[b + j + 4];
            a[b + j]     = cadd(u, v);
            a[b + j + 4] = cmul(csub(u, v), W[2 * j]);
        }
    #pragma unroll
    for (int b = 0; b < 16; b += 4)
        #pragma unroll
        for (int j = 0; j < 2; j++) {
            float2 u = a[b + j], v = a[b + j + 2];
            float2 t = csub(u, v);
            a[b + j]     = cadd(u, v);
            a[b + j + 2] = (j == 0) ? t : make_float2(t.y, -t.x);   // * (0,-1)
        }
    #pragma unroll
    for (int b = 0; b < 16; b += 2) {
        float2 u = a[b], v = a[b + 1];
        a[b]     = cadd(u, v);
        a[b + 1] = csub(u, v);
    }
}

// ---------------------------------------------------------------------------
// Kernel 0: build cos/sin table for reconstruction (~2us)
// ---------------------------------------------------------------------------
__global__ __launch_bounds__(256) void init_tables() {
    const int gtid = blockIdx.x * 256 + threadIdx.x;   // 0..4095
    float s, c;
    sincosf((float)gtid * (TWO_PI / (float)N_T), &s, &c);
    g_cs[gtid] = make_float2(c, s);
}

// ---------------------------------------------------------------------------
// Kernel T: x[b,t,d] -> g_xT[b*256+d][t] via 32x33 smem tiles (coalesced both ways)
// ---------------------------------------------------------------------------
__global__ __launch_bounds__(256) void transpose_kernel(const float* __restrict__ x) {
    __shared__ float tile[32][33];
    const int b  = blockIdx.z;
    const int tt = blockIdx.x;   // t tile
    const int dd = blockIdx.y;   // d tile
    const int tx = threadIdx.x & 31;
    const int ty = threadIdx.x >> 5;   // 0..7

    const float* xp = x + ((size_t)b * N_T + (size_t)tt * 32) * N_D + (size_t)dd * 32;
    #pragma unroll
    for (int r = 0; r < 32; r += 8)
        tile[ty + r][tx] = xp[(size_t)(ty + r) * N_D + tx];
    __syncthreads();

    float* op = g_xT + ((size_t)(b * N_D + dd * 32)) * N_T + (size_t)tt * 32;
    #pragma unroll
    for (int r = 0; r < 32; r += 8)
        op[(size_t)(ty + r) * N_T + tx] = tile[tx][ty + r];
}

// ---------------------------------------------------------------------------
// Kernel A: per-column 4096-pt FFT (3 radix-16 passes, registers) + top-7
// ---------------------------------------------------------------------------
__global__ __launch_bounds__(256, 4) void fft_topk_kernel() {
    __shared__ float2 s_buf[PAD(4095) + 1];   // 4351 float2 = 34.8 KB
    __shared__ float  s_mag[2048];
    __shared__ float  s_redv[8];
    __shared__ int    s_redi[8];

    const int tid = threadIdx.x;
    const int col = blockIdx.x;
    const float* xp = g_xT + (size_t)col * N_T;

    const int BR[16] = {0,8,4,12,2,10,6,14,1,9,5,13,3,11,7,15};
    float2 a[16];

    // ---- pass 0: DFT over n1 (stride 256), post-twiddle W4096^{tid*k0} ----
    #pragma unroll
    for (int n1 = 0; n1 < 16; n1++)
        a[n1] = make_float2(__ldg(xp + 256 * n1 + tid), 0.0f);   // coalesced
    fft16(a);
    {
        float sn, cn;
        sincosf(-(TWO_PI / 4096.0f) * (float)tid, &sn, &cn);
        const float2 w = make_float2(cn, sn);                    // e^{-2pi i tid/4096}
        float2 tw = make_float2(1.0f, 0.0f);
        #pragma unroll
        for (int r = 0; r < 16; r++) {
            s_buf[PAD(256 * r + tid)] = cmul(a[BR[r]], tw);
            tw = cmul(tw, w);
        }
    }
    __syncthreads();

    // ---- pass 1: DFT over m1 (stride 16), post-twiddle W256^{m0*k1} ----
    const int k0 = tid >> 4, m0 = tid & 15;
    #pragma unroll
    for (int m1 = 0; m1 < 16; m1++)
        a[m1] = s_buf[PAD(256 * k0 + 16 * m1 + m0)];
    fft16(a);
    {
        float sn, cn;
        sincosf(-(TWO_PI / 256.0f) * (float)m0, &sn, &cn);
        const float2 w = make_float2(cn, sn);                    // e^{-2pi i m0/256}
        float2 tw = make_float2(1.0f, 0.0f);
        #pragma unroll
        for (int r = 0; r < 16; r++) {
            s_buf[PAD(256 * k0 + 16 * r + m0)] = cmul(a[BR[r]], tw);   // own slots only
            tw = cmul(tw, w);
        }
    }
    __syncthreads();

    // ---- pass 2: DFT over m0 (stride 1); bin f = k0 + 16*k1 + 256*k2 ----
    const int kk1 = tid & 15;   // k0 is tid>>4 (same var)
    #pragma unroll
    for (int m = 0; m < 16; m++)
        a[m] = s_buf[PAD(256 * k0 + 16 * kk1 + m)];
    fft16(a);
    __syncthreads();   // everyone done reading s_buf before we repurpose it

    // spectrum (f < 2048) back into the dead pass buffer + magnitudes
    const int fbase = k0 + 16 * kk1;
    #pragma unroll
    for (int r = 0; r < 8; r++) {
        const float2 X = a[BR[r]];
        const int f = fbase + 256 * r;
        s_buf[PAD(f)] = X;
        s_mag[f] = (f == 0) ? -1e30f : fmaf(X.x, X.x, X.y * X.y);
    }
    __syncthreads();

    // ---- 7 rounds of block argmax (ties -> lowest index, matching lax.top_k) ----
    for (int sel = 0; sel < TOPK; sel++) {
        float bv = -1e30f; int bi = 0;
        for (int f = tid; f < 2048; f += 256) {
            const float v = s_mag[f];
            if (v > bv) { bv = v; bi = f; }   // ascending scan keeps lowest idx
        }
        #pragma unroll
        for (int off = 16; off > 0; off >>= 1) {
            const float ov = __shfl_down_sync(0xffffffffu, bv, off);
            const int   oi = __shfl_down_sync(0xffffffffu, bi, off);
            if (ov > bv || (ov == bv && oi < bi)) { bv = ov; bi = oi; }
        }
        if ((tid & 31) == 0) { s_redv[tid >> 5] = bv; s_redi[tid >> 5] = bi; }
        __syncthreads();
        if (tid == 0) {
            for (int w = 1; w < 8; w++) {
                const float ov = s_redv[w]; const int oi = s_redi[w];
                if (ov > bv || (ov == bv && oi < bi)) { bv = ov; bi = oi; }
            }
            const float2 X = s_buf[PAD(bi)];
            const float sc = 4.0f / (float)N_T;       // 2/T amp * 2 conj pair
            g_Ac[col * TOPK + sel]  = sc * X.x;       // A*cos(phi) = (4/T)*Re
            g_As[col * TOPK + sel]  = sc * X.y;       // A*sin(phi) = (4/T)*Im
            g_idx[col * TOPK + sel] = bi;
            s_mag[bi] = -1e30f;
        }
        __syncthreads();
    }
}

// ---------------------------------------------------------------------------
// Kernel B: reconstruction via complex-rotation recurrence (no per-output LDS).
//   out[b,t,d] = sum_k Ac_k*cos(th_k*t) - As_k*sin(th_k*t),  th_k = 2pi*idx_k/4096
//   Per thread: start (cos,sin) at t0 and step (cos th, sin th) from smem table
//   (14 LDS total), then 32 outputs of pure FMA rotation.
// Grid: (128 t-tiles of 32, 16 b). threadIdx.x = d (coalesced stores).
// ---------------------------------------------------------------------------
__global__ __launch_bounds__(256) void recon_kernel(float* __restrict__ out) {
    __shared__ float2 tab[N_T];   // {cos, sin}(2*pi*m/4096)

    const int tid = threadIdx.x;
    for (int m = tid; m < N_T; m += 256)
        tab[m] = __ldg(&g_cs[m]);
    __syncthreads();

    const int b  = blockIdx.y;
    const int t0 = blockIdx.x * 32;
    const int d  = tid;
    const int col = b * N_D + d;

    float Ac[TOPK], Asn[TOPK];
    float c[TOPK], s[TOPK], cs[TOPK], ss[TOPK];
    #pragma unroll
    for (int k = 0; k < TOPK; k++) {
        Ac[k]  =  g_Ac[col * TOPK + k];
        Asn[k] = -g_As[col * TOPK + k];
        const int idx = g_idx[col * TOPK + k];
        const float2 p0 = tab[(idx * t0) & (N_T - 1)];   // phase at t0
        const float2 st = tab[idx];                       // step rotation
        c[k] = p0.x;  s[k] = p0.y;
        cs[k] = st.x; ss[k] = st.y;
    }

    float* outp = out + ((size_t)b * N_T + t0) * N_D + d;
    #pragma unroll
    for (int tt = 0; tt < 32; tt++) {
        float acc = 0.0f;
        #pragma unroll
        for (int k = 0; k < TOPK; k++) {
            acc = fmaf(Ac[k],  c[k], acc);
            acc = fmaf(Asn[k], s[k], acc);
            const float nc = fmaf(c[k], cs[k], -(s[k] * ss[k]));
            const float ns = fmaf(c[k], ss[k],   s[k] * cs[k]);
            c[k] = nc; s[k] = ns;
        }
        outp[(size_t)tt * N_D] = acc;
    }
}

// ---------------------------------------------------------------------------
extern "C" void kernel_launch(void* const* d_in, const int* in_sizes, int n_in,
                              void* d_out, int out_size) {
    const float* x = (const float*)d_in[0];
    float* out = (float*)d_out;

    init_tables<<<16, 256>>>();
    transpose_kernel<<<dim3(N_T / 32, N_D / 32, N_B), 256>>>(x);
    fft_topk_kernel<<<NCOL, 256>>>();
    recon_kernel<<<dim3(N_T / 32, N_B), 256>>>(out);
}

// round 10
// speedup vs baseline: 4.6867x; 1.1460x over previous
#include <cuda_runtime.h>

#define N_T   4096
#define N_D   256
#define N_B   16
#define NCOL  (N_B * N_D)     // 4096 columns (b,d)
#define NPAIR (NCOL / 2)      // 2048 column pairs (d even/odd adjacent)
#define TOPK  7
#define TWO_PI 6.28318530717958647692f

// Per-column selected-frequency parameters (scratch; device globals per rules)
__device__ float g_Ac[NCOL * TOPK];
__device__ float g_As[NCOL * TOPK];
__device__ int   g_idx[NCOL * TOPK];

// cos/sin master table for reconstruction
__device__ float2 g_cs[N_T];

// 64 MB transposed input: g_xT2[pair][t] = (x[b,t,2p], x[b,t,2p+1]) as complex
__device__ float2 g_xT2[(size_t)NPAIR * N_T];

// padded smem index: injective, kills stride-16 conflicts in passes 1/2
#define PAD(n) ((n) + ((n) >> 4))

typedef unsigned long long u64;
__device__ __forceinline__ u64 pack2(float lo, float hi) {
    u64 r; asm("mov.b64 %0, {%1, %2};" : "=l"(r) : "f"(lo), "f"(hi)); return r;
}
__device__ __forceinline__ void unpack2(u64 v, float& lo, float& hi) {
    asm("mov.b64 {%0, %1}, %2;" : "=f"(lo), "=f"(hi) : "l"(v));
}
__device__ __forceinline__ u64 fma2(u64 a, u64 b, u64 c) {
    u64 r; asm("fma.rn.f32x2 %0, %1, %2, %3;" : "=l"(r) : "l"(a), "l"(b), "l"(c)); return r;
}
__device__ __forceinline__ u64 mul2(u64 a, u64 b) {
    u64 r; asm("mul.rn.f32x2 %0, %1, %2;" : "=l"(r) : "l"(a), "l"(b)); return r;
}
__device__ __forceinline__ u64 add2(u64 a, u64 b) {
    u64 r; asm("add.rn.f32x2 %0, %1, %2;" : "=l"(r) : "l"(a), "l"(b)); return r;
}

__device__ __forceinline__ float2 cmul(float2 a, float2 b) {
    return make_float2(fmaf(a.x, b.x, -(a.y * b.y)),
                       fmaf(a.x, b.y,   a.y * b.x));
}
__device__ __forceinline__ float2 cadd(float2 a, float2 b) { return make_float2(a.x + b.x, a.y + b.y); }
__device__ __forceinline__ float2 csub(float2 a, float2 b) { return make_float2(a.x - b.x, a.y - b.y); }

// 16-pt DIF FFT in registers; X[k] ends up in a[bitrev4(k)].
__device__ __forceinline__ void fft16(float2 a[16]) {
    const float c1 = 0.9238795325112867f;
    const float s1 = 0.3826834323650898f;
    const float r2 = 0.7071067811865476f;
    const float2 W[8] = { { 1.f, 0.f}, { c1, -s1}, { r2, -r2}, { s1, -c1},
                          { 0.f,-1.f}, {-s1, -c1}, {-r2, -r2}, {-c1, -s1} };
    #pragma unroll
    for (int j = 0; j < 8; j++) {
        float2 u = a[j], v = a[j + 8];
        a[j]     = cadd(u, v);
        a[j + 8] = cmul(csub(u, v), W[j]);
    }
    #pragma unroll
    for (int b = 0; b < 16; b += 8)
        #pragma unroll
        for (int j = 0; j < 4; j++) {
            float2 u = a[b + j], v = a[b + j + 4];
            a[b + j]     = cadd(u, v);
            a[b + j + 4] = cmul(csub(u, v), W[2 * j]);
        }
    #pragma unroll
    for (int b = 0; b < 16; b += 4)
        #pragma unroll
        for (int j = 0; j < 2; j++) {
            float2 u = a[b + j], v = a[b + j + 2];
            float2 t = csub(u, v);
            a[b + j]     = cadd(u, v);
            a[b + j + 2] = (j == 0) ? t : make_float2(t.y, -t.x);
        }
    #pragma unroll
    for (int b = 0; b < 16; b += 2) {
        float2 u = a[b], v = a[b + 1];
        a[b]     = cadd(u, v);
        a[b + 1] = csub(u, v);
    }
}

// ---------------------------------------------------------------------------
// Kernel 0: build cos/sin table for reconstruction
// ---------------------------------------------------------------------------
__global__ __launch_bounds__(256) void init_tables() {
    const int gtid = blockIdx.x * 256 + threadIdx.x;
    float s, c;
    sincosf((float)gtid * (TWO_PI / (float)N_T), &s, &c);
    g_cs[gtid] = make_float2(c, s);
}

// ---------------------------------------------------------------------------
// Kernel T: x[b,t,2p..2p+1] -> g_xT2[b*128+p][t] via 32x33 float2 smem tiles
// ---------------------------------------------------------------------------
__global__ __launch_bounds__(256) void transpose_kernel(const float* __restrict__ x) {
    __shared__ float2 tile[32][33];
    const int b  = blockIdx.z;
    const int tt = blockIdx.x;   // t tile (32)
    const int pp = blockIdx.y;   // pair tile (32)
    const int tx = threadIdx.x & 31;
    const int ty = threadIdx.x >> 5;   // 0..7

    const float2* xp = (const float2*)x + ((size_t)b * N_T + (size_t)tt * 32) * 128 + (size_t)pp * 32;
    #pragma unroll
    for (int r = 0; r < 32; r += 8)
        tile[ty + r][tx] = xp[(size_t)(ty + r) * 128 + tx];
    __syncthreads();

    float2* op = g_xT2 + ((size_t)(b * 128 + pp * 32)) * N_T + (size_t)tt * 32;
    #pragma unroll
    for (int r = 0; r < 32; r += 8)
        op[(size_t)(ty + r) * N_T + tx] = tile[tx][ty + r];
}

// ---------------------------------------------------------------------------
// Kernel A: one 4096-pt complex FFT per column PAIR (3 radix-16 passes),
// then real-FFT unpack + two top-7 selections.
// ---------------------------------------------------------------------------
__global__ __launch_bounds__(256, 4) void fft_topk_kernel() {
    __shared__ float2 s_buf[PAD(4095) + 1];   // full spectrum, 34.8 KB
    __shared__ float  s_mag[2048];            // one column at a time, 8 KB
    __shared__ float  s_redv[8];
    __shared__ int    s_redi[8];

    const int tid  = threadIdx.x;
    const int pair = blockIdx.x;
    const float2* xp = g_xT2 + (size_t)pair * N_T;

    const int BR[16] = {0,8,4,12,2,10,6,14,1,9,5,13,3,11,7,15};
    float2 a[16];

    // ---- pass 0: DFT over n1 (stride 256), post-twiddle W4096^{tid*k0} ----
    #pragma unroll
    for (int n1 = 0; n1 < 16; n1++)
        a[n1] = __ldg(xp + 256 * n1 + tid);   // complex input, coalesced
    fft16(a);
    {
        float sn, cn;
        sincosf(-(TWO_PI / 4096.0f) * (float)tid, &sn, &cn);
        const float2 w = make_float2(cn, sn);
        float2 tw = make_float2(1.0f, 0.0f);
        #pragma unroll
        for (int r = 0; r < 16; r++) {
            s_buf[PAD(256 * r + tid)] = cmul(a[BR[r]], tw);
            tw = cmul(tw, w);
        }
    }
    __syncthreads();

    // ---- pass 1: DFT over m1 (stride 16), post-twiddle W256^{m0*k1} ----
    const int k0 = tid >> 4, m0 = tid & 15;
    #pragma unroll
    for (int m1 = 0; m1 < 16; m1++)
        a[m1] = s_buf[PAD(256 * k0 + 16 * m1 + m0)];
    fft16(a);
    {
        float sn, cn;
        sincosf(-(TWO_PI / 256.0f) * (float)m0, &sn, &cn);
        const float2 w = make_float2(cn, sn);
        float2 tw = make_float2(1.0f, 0.0f);
        #pragma unroll
        for (int r = 0; r < 16; r++) {
            s_buf[PAD(256 * k0 + 16 * r + m0)] = cmul(a[BR[r]], tw);
            tw = cmul(tw, w);
        }
    }
    __syncthreads();

    // ---- pass 2: DFT over m0 (stride 1); bin f = k0 + 16*k1 + 256*k2 ----
    const int kk1 = tid & 15;
    #pragma unroll
    for (int m = 0; m < 16; m++)
        a[m] = s_buf[PAD(256 * k0 + 16 * kk1 + m)];
    fft16(a);
    __syncthreads();   // all reads of s_buf done before overwrite

    // full spectrum Z[0..4095] back into s_buf (natural bin order)
    const int fbase = k0 + 16 * kk1;
    #pragma unroll
    for (int r = 0; r < 16; r++)
        s_buf[PAD(fbase + 256 * r)] = a[BR[r]];
    __syncthreads();

    // ---- per column of the pair: unpack mags, then 7 argmax rounds ----
    const float sc = 2.0f / (float)N_T;   // (4/T amp) * (1/2 unpack)
    for (int cc = 0; cc < 2; cc++) {
        for (int f = tid; f < 2048; f += 256) {
            float m2 = -1e30f;
            if (f != 0) {
                const float2 Z1 = s_buf[PAD(f)];
                const float2 Z2 = s_buf[PAD(4096 - f)];
                float re, im;
                if (cc == 0) { re = Z1.x + Z2.x; im = Z1.y - Z2.y; }
                else         { re = Z1.y + Z2.y; im = Z2.x - Z1.x; }
                m2 = fmaf(re, re, im * im);
            }
            s_mag[f] = m2;
        }
        __syncthreads();

        const int col = 2 * pair + cc;
        for (int sel = 0; sel < TOPK; sel++) {
            float bv = -1e30f; int bi = 0;
            for (int f = tid; f < 2048; f += 256) {
                const float v = s_mag[f];
                if (v > bv) { bv = v; bi = f; }   // ascending scan keeps lowest idx
            }
            #pragma unroll
            for (int off = 16; off > 0; off >>= 1) {
                const float ov = __shfl_down_sync(0xffffffffu, bv, off);
                const int   oi = __shfl_down_sync(0xffffffffu, bi, off);
                if (ov > bv || (ov == bv && oi < bi)) { bv = ov; bi = oi; }
            }
            if ((tid & 31) == 0) { s_redv[tid >> 5] = bv; s_redi[tid >> 5] = bi; }
            __syncthreads();
            if (tid == 0) {
                for (int w = 1; w < 8; w++) {
                    const float ov = s_redv[w]; const int oi = s_redi[w];
                    if (ov > bv || (ov == bv && oi < bi)) { bv = ov; bi = oi; }
                }
                const float2 Z1 = s_buf[PAD(bi)];
                const float2 Z2 = s_buf[PAD(4096 - bi)];
                float re, im;
                if (cc == 0) { re = Z1.x + Z2.x; im = Z1.y - Z2.y; }
                else         { re = Z1.y + Z2.y; im = Z2.x - Z1.x; }
                g_Ac[col * TOPK + sel]  = sc * re;
                g_As[col * TOPK + sel]  = sc * im;
                g_idx[col * TOPK + sel] = bi;
                s_mag[bi] = -1e30f;
            }
            __syncthreads();
        }
    }
}

// ---------------------------------------------------------------------------
// Kernel B: reconstruction via f32x2-packed complex-rotor recurrence.
//   v_k(t) = (Ac_k + i As_k) e^{i th_k t};  out = sum_k Re(v_k);
//   v advances by constant rotor per t. 7 oscillators + 1 dummy -> 4 f32x2 lanes.
// ---------------------------------------------------------------------------
__global__ __launch_bounds__(256) void recon_kernel(float* __restrict__ out) {
    __shared__ float2 tab[N_T];

    const int tid = threadIdx.x;
    for (int m = tid; m < N_T; m += 256)
        tab[m] = __ldg(&g_cs[m]);
    __syncthreads();

    const int b  = blockIdx.y;
    const int t0 = blockIdx.x * 32;
    const int d  = tid;
    const int col = b * N_D + d;

    float urk[8], uik[8], csk[8], ssk[8];
    #pragma unroll
    for (int k = 0; k < 8; k++) {
        if (k < TOPK) {
            const float Acv = g_Ac[col * TOPK + k];
            const float Asv = g_As[col * TOPK + k];
            const int idx   = g_idx[col * TOPK + k];
            const float2 p0 = tab[(idx * t0) & (N_T - 1)];
            const float2 st = tab[idx];
            urk[k] = Acv * p0.x - Asv * p0.y;   // Re((Ac+iAs) e^{i th t0})
            uik[k] = Acv * p0.y + Asv * p0.x;   // Im
            csk[k] = st.x; ssk[k] = st.y;
        } else {
            urk[k] = 0.0f; uik[k] = 0.0f; csk[k] = 1.0f; ssk[k] = 0.0f;
        }
    }

    u64 ur[4], ui[4], cs2[4], ss2[4], nss2[4];
    #pragma unroll
    for (int p = 0; p < 4; p++) {
        ur[p]   = pack2(urk[2*p],  urk[2*p+1]);
        ui[p]   = pack2(uik[2*p],  uik[2*p+1]);
        cs2[p]  = pack2(csk[2*p],  csk[2*p+1]);
        ss2[p]  = pack2(ssk[2*p],  ssk[2*p+1]);
        nss2[p] = pack2(-ssk[2*p], -ssk[2*p+1]);
    }

    float* outp = out + ((size_t)b * N_T + t0) * N_D + d;
    #pragma unroll
    for (int tt = 0; tt < 32; tt++) {
        u64 acc = pack2(0.0f, 0.0f);
        #pragma unroll
        for (int p = 0; p < 4; p++) {
            acc = add2(acc, ur[p]);
            const u64 t1 = mul2(ur[p], cs2[p]);
            const u64 t2 = mul2(ur[p], ss2[p]);
            ur[p] = fma2(ui[p], nss2[p], t1);   // ur' = ur*cs - ui*ss
            ui[p] = fma2(ui[p], cs2[p],  t2);   // ui' = ur*ss + ui*cs
        }
        float lo, hi; unpack2(acc, lo, hi);
        outp[(size_t)tt * N_D] = lo + hi;
    }
}

// ---------------------------------------------------------------------------
extern "C" void kernel_launch(void* const* d_in, const int* in_sizes, int n_in,
                              void* d_out, int out_size) {
    const float* x = (const float*)d_in[0];
    float* out = (float*)d_out;

    init_tables<<<16, 256>>>();
    transpose_kernel<<<dim3(N_T / 32, 4, N_B), 256>>>(x);
    fft_topk_kernel<<<NPAIR, 256>>>();
    recon_kernel<<<dim3(N_T / 32, N_B), 256>>>(out);
}

// round 12
// speedup vs baseline: 5.1613x; 1.1013x over previous
#include <cuda_runtime.h>

#define N_T   4096
#define N_D   256
#define N_B   16
#define NCOL  (N_B * N_D)     // 4096 columns (b,d)
#define NPAIR (NCOL / 2)      // 2048 column pairs (d even/odd adjacent)
#define TOPK  7
#define TS    128             // recon t-tile
#define TWO_PI 6.28318530717958647692f

// Per-column selected-frequency parameters (scratch; device globals per rules)
__device__ float g_Ac[NCOL * TOPK];
__device__ float g_As[NCOL * TOPK];
__device__ int   g_idx[NCOL * TOPK];

// cos/sin master table for reconstruction
__device__ float2 g_cs[N_T];

// 64 MB transposed input: g_xT2[pair][t] = (x[b,t,2p], x[b,t,2p+1]) as complex
__device__ float2 g_xT2[(size_t)NPAIR * N_T];

// padded smem index: injective, kills stride-16 conflicts in passes 1/2
#define PAD(n) ((n) + ((n) >> 4))

typedef unsigned long long u64;
__device__ __forceinline__ u64 pack2(float lo, float hi) {
    u64 r; asm("mov.b64 %0, {%1, %2};" : "=l"(r) : "f"(lo), "f"(hi)); return r;
}
__device__ __forceinline__ void unpack2(u64 v, float& lo, float& hi) {
    asm("mov.b64 {%0, %1}, %2;" : "=f"(lo), "=f"(hi) : "l"(v));
}
__device__ __forceinline__ u64 fma2(u64 a, u64 b, u64 c) {
    u64 r; asm("fma.rn.f32x2 %0, %1, %2, %3;" : "=l"(r) : "l"(a), "l"(b), "l"(c)); return r;
}
__device__ __forceinline__ u64 mul2(u64 a, u64 b) {
    u64 r; asm("mul.rn.f32x2 %0, %1, %2;" : "=l"(r) : "l"(a), "l"(b)); return r;
}
__device__ __forceinline__ u64 add2(u64 a, u64 b) {
    u64 r; asm("add.rn.f32x2 %0, %1, %2;" : "=l"(r) : "l"(a), "l"(b)); return r;
}

__device__ __forceinline__ float2 cmul(float2 a, float2 b) {
    return make_float2(fmaf(a.x, b.x, -(a.y * b.y)),
                       fmaf(a.x, b.y,   a.y * b.x));
}
__device__ __forceinline__ float2 cadd(float2 a, float2 b) { return make_float2(a.x + b.x, a.y + b.y); }
__device__ __forceinline__ float2 csub(float2 a, float2 b) { return make_float2(a.x - b.x, a.y - b.y); }

// 16-pt DIF FFT in registers; X[k] ends up in a[bitrev4(k)].
__device__ __forceinline__ void fft16(float2 a[16]) {
    const float c1 = 0.9238795325112867f;
    const float s1 = 0.3826834323650898f;
    const float r2 = 0.7071067811865476f;
    const float2 W[8] = { { 1.f, 0.f}, { c1, -s1}, { r2, -r2}, { s1, -c1},
                          { 0.f,-1.f}, {-s1, -c1}, {-r2, -r2}, {-c1, -s1} };
    #pragma unroll
    for (int j = 0; j < 8; j++) {
        float2 u = a[j], v = a[j + 8];
        a[j]     = cadd(u, v);
        a[j + 8] = cmul(csub(u, v), W[j]);
    }
    #pragma unroll
    for (int b = 0; b < 16; b += 8)
        #pragma unroll
        for (int j = 0; j < 4; j++) {
            float2 u = a[b + j], v = a[b + j + 4];
            a[b + j]     = cadd(u, v);
            a[b + j + 4] = cmul(csub(u, v), W[2 * j]);
        }
    #pragma unroll
    for (int b = 0; b < 16; b += 4)
        #pragma unroll
        for (int j = 0; j < 2; j++) {
            float2 u = a[b + j], v = a[b + j + 2];
            float2 t = csub(u, v);
            a[b + j]     = cadd(u, v);
            a[b + j + 2] = (j == 0) ? t : make_float2(t.y, -t.x);
        }
    #pragma unroll
    for (int b = 0; b < 16; b += 2) {
        float2 u = a[b], v = a[b + 1];
        a[b]     = cadd(u, v);
        a[b + 1] = csub(u, v);
    }
}

// ---------------------------------------------------------------------------
// Kernel T: x[b,t,2p..2p+1] -> g_xT2[b*128+p][t] via 32x33 float2 smem tiles.
// First 16 CTAs also build the cos/sin master table (folds init kernel away).
// ---------------------------------------------------------------------------
__global__ __launch_bounds__(256) void transpose_kernel(const float* __restrict__ x) {
    __shared__ float2 tile[32][33];
    const int b  = blockIdx.z;
    const int tt = blockIdx.x;   // t tile (32)
    const int pp = blockIdx.y;   // pair tile (32)
    const int tx = threadIdx.x & 31;
    const int ty = threadIdx.x >> 5;   // 0..7

    if (b == 0 && pp == 0 && tt < 16) {   // build g_cs alongside
        const int gtid = tt * 256 + threadIdx.x;
        float s, c;
        sincosf((float)gtid * (TWO_PI / (float)N_T), &s, &c);
        g_cs[gtid] = make_float2(c, s);
    }

    const float2* xp = (const float2*)x + ((size_t)b * N_T + (size_t)tt * 32) * 128 + (size_t)pp * 32;
    #pragma unroll
    for (int r = 0; r < 32; r += 8)
        tile[ty + r][tx] = xp[(size_t)(ty + r) * 128 + tx];
    __syncthreads();

    float2* op = g_xT2 + ((size_t)(b * 128 + pp * 32)) * N_T + (size_t)tt * 32;
    #pragma unroll
    for (int r = 0; r < 32; r += 8)
        op[(size_t)(ty + r) * N_T + tx] = tile[tx][ty + r];
}

// ---------------------------------------------------------------------------
// Kernel A: one 4096-pt complex FFT per column PAIR (3 radix-16 passes),
// then real-FFT unpack + two top-7 selections.
// ---------------------------------------------------------------------------
__global__ __launch_bounds__(256, 4) void fft_topk_kernel() {
    __shared__ float2 s_buf[PAD(4095) + 1];   // full spectrum, 34.8 KB
    __shared__ float  s_mag[2048];            // one column at a time, 8 KB
    __shared__ float  s_redv[8];
    __shared__ int    s_redi[8];

    const int tid  = threadIdx.x;
    const int pair = blockIdx.x;
    const float2* xp = g_xT2 + (size_t)pair * N_T;

    const int BR[16] = {0,8,4,12,2,10,6,14,1,9,5,13,3,11,7,15};
    float2 a[16];

    // ---- pass 0: DFT over n1 (stride 256), post-twiddle W4096^{tid*k0} ----
    #pragma unroll
    for (int n1 = 0; n1 < 16; n1++)
        a[n1] = __ldg(xp + 256 * n1 + tid);   // complex input, coalesced
    fft16(a);
    {
        float sn, cn;
        __sincosf(-(TWO_PI / 4096.0f) * (float)tid, &sn, &cn);   // |x|<0.4 rad
        const float2 w = make_float2(cn, sn);
        float2 tw = make_float2(1.0f, 0.0f);
        #pragma unroll
        for (int r = 0; r < 16; r++) {
            s_buf[PAD(256 * r + tid)] = cmul(a[BR[r]], tw);
            tw = cmul(tw, w);
        }
    }
    __syncthreads();

    // ---- pass 1: DFT over m1 (stride 16), post-twiddle W256^{m0*k1} ----
    const int k0 = tid >> 4, m0 = tid & 15;
    #pragma unroll
    for (int m1 = 0; m1 < 16; m1++)
        a[m1] = s_buf[PAD(256 * k0 + 16 * m1 + m0)];
    fft16(a);
    {
        float sn, cn;
        __sincosf(-(TWO_PI / 256.0f) * (float)m0, &sn, &cn);     // |x|<0.4 rad
        const float2 w = make_float2(cn, sn);
        float2 tw = make_float2(1.0f, 0.0f);
        #pragma unroll
        for (int r = 0; r < 16; r++) {
            s_buf[PAD(256 * k0 + 16 * r + m0)] = cmul(a[BR[r]], tw);
            tw = cmul(tw, w);
        }
    }
    __syncthreads();

    // ---- pass 2: DFT over m0 (stride 1); bin f = k0 + 16*k1 + 256*k2 ----
    const int kk1 = tid & 15;
    #pragma unroll
    for (int m = 0; m < 16; m++)
        a[m] = s_buf[PAD(256 * k0 + 16 * kk1 + m)];
    fft16(a);
    __syncthreads();   // all reads of s_buf done before overwrite

    // full spectrum Z[0..4095] back into s_buf (natural bin order)
    const int fbase = k0 + 16 * kk1;
    #pragma unroll
    for (int r = 0; r < 16; r++)
        s_buf[PAD(fbase + 256 * r)] = a[BR[r]];
    __syncthreads();

    // ---- per column of the pair: unpack mags, then 7 argmax rounds ----
    const float sc = 2.0f / (float)N_T;   // (4/T amp) * (1/2 unpack)
    for (int cc = 0; cc < 2; cc++) {
        for (int f = tid; f < 2048; f += 256) {
            float m2 = -1e30f;
            if (f != 0) {
                const float2 Z1 = s_buf[PAD(f)];
                const float2 Z2 = s_buf[PAD(4096 - f)];
                float re, im;
                if (cc == 0) { re = Z1.x + Z2.x; im = Z1.y - Z2.y; }
                else         { re = Z1.y + Z2.y; im = Z2.x - Z1.x; }
                m2 = fmaf(re, re, im * im);
            }
            s_mag[f] = m2;
        }
        __syncthreads();

        const int col = 2 * pair + cc;
        for (int sel = 0; sel < TOPK; sel++) {
            float bv = -1e30f; int bi = 0;
            for (int f = tid; f < 2048; f += 256) {
                const float v = s_mag[f];
                if (v > bv) { bv = v; bi = f; }   // ascending scan keeps lowest idx
            }
            #pragma unroll
            for (int off = 16; off > 0; off >>= 1) {
                const float ov = __shfl_down_sync(0xffffffffu, bv, off);
                const int   oi = __shfl_down_sync(0xffffffffu, bi, off);
                if (ov > bv || (ov == bv && oi < bi)) { bv = ov; bi = oi; }
            }
            if ((tid & 31) == 0) { s_redv[tid >> 5] = bv; s_redi[tid >> 5] = bi; }
            __syncthreads();
            if (tid == 0) {
                for (int w = 1; w < 8; w++) {
                    const float ov = s_redv[w]; const int oi = s_redi[w];
                    if (ov > bv || (ov == bv && oi < bi)) { bv = ov; bi = oi; }
                }
                const float2 Z1 = s_buf[PAD(bi)];
                const float2 Z2 = s_buf[PAD(4096 - bi)];
                float re, im;
                if (cc == 0) { re = Z1.x + Z2.x; im = Z1.y - Z2.y; }
                else         { re = Z1.y + Z2.y; im = Z2.x - Z1.x; }
                g_Ac[col * TOPK + sel]  = sc * re;
                g_As[col * TOPK + sel]  = sc * im;
                g_idx[col * TOPK + sel] = bi;
                s_mag[bi] = -1e30f;
            }
            __syncthreads();
        }
    }
}

// ---------------------------------------------------------------------------
// Kernel B: reconstruction via f32x2-packed complex-rotor recurrence.
//   v_k(t) = (Ac_k + i As_k) e^{i th_k t};  out = sum_k Re(v_k);
//   TS=128 outputs per thread amortizes the smem table load 4x vs TS=32.
// ---------------------------------------------------------------------------
__global__ __launch_bounds__(256) void recon_kernel(float* __restrict__ out) {
    __shared__ float2 tab[N_T];

    const int tid = threadIdx.x;
    for (int m = tid; m < N_T; m += 256)
        tab[m] = __ldg(&g_cs[m]);
    __syncthreads();

    const int b  = blockIdx.y;
    const int t0 = blockIdx.x * TS;
    const int d  = tid;
    const int col = b * N_D + d;

    float urk[8], uik[8], csk[8], ssk[8];
    #pragma unroll
    for (int k = 0; k < 8; k++) {
        if (k < TOPK) {
            const float Acv = g_Ac[col * TOPK + k];
            const float Asv = g_As[col * TOPK + k];
            const int idx   = g_idx[col * TOPK + k];
            const float2 p0 = tab[(idx * t0) & (N_T - 1)];
            const float2 st = tab[idx];
            urk[k] = Acv * p0.x - Asv * p0.y;   // Re((Ac+iAs) e^{i th t0})
            uik[k] = Acv * p0.y + Asv * p0.x;   // Im
            csk[k] = st.x; ssk[k] = st.y;
        } else {
            urk[k] = 0.0f; uik[k] = 0.0f; csk[k] = 1.0f; ssk[k] = 0.0f;
        }
    }

    u64 ur[4], ui[4], cs2[4], ss2[4], nss2[4];
    #pragma unroll
    for (int p = 0; p < 4; p++) {
        ur[p]   = pack2(urk[2*p],  urk[2*p+1]);
        ui[p]   = pack2(uik[2*p],  uik[2*p+1]);
        cs2[p]  = pack2(csk[2*p],  csk[2*p+1]);
        ss2[p]  = pack2(ssk[2*p],  ssk[2*p+1]);
        nss2[p] = pack2(-ssk[2*p], -ssk[2*p+1]);
    }

    float* outp = out + ((size_t)b * N_T + t0) * N_D + d;
    #pragma unroll 8
    for (int tt = 0; tt < TS; tt++) {
        u64 acc = add2(ur[0], ur[1]);
        acc = add2(acc, add2(ur[2], ur[3]));
        #pragma unroll
        for (int p = 0; p < 4; p++) {
            const u64 t1 = mul2(ur[p], cs2[p]);
            const u64 t2 = mul2(ur[p], ss2[p]);
            ur[p] = fma2(ui[p], nss2[p], t1);   // ur' = ur*cs - ui*ss
            ui[p] = fma2(ui[p], cs2[p],  t2);   // ui' = ur*ss + ui*cs
        }
        float lo, hi; unpack2(acc, lo, hi);
        outp[(size_t)tt * N_D] = lo + hi;
    }
}

// ---------------------------------------------------------------------------
extern "C" void kernel_launch(void* const* d_in, const int* in_sizes, int n_in,
                              void* d_out, int out_size) {
    const float* x = (const float*)d_in[0];
    float* out = (float*)d_out;

    transpose_kernel<<<dim3(N_T / 32, 4, N_B), 256>>>(x);
    fft_topk_kernel<<<NPAIR, 256>>>();
    recon_kernel<<<dim3(N_T / TS, N_B), 256>>>(out);
}